// round 6
// baseline (speedup 1.0000x reference)
#include <cuda_runtime.h>
#include <cuda_fp16.h>
#include <cstdint>

// Problem constants (fixed by setup_inputs)
#define NIMG   16
#define CIN    128
#define COUT   256
#define HDIM   112
#define WDIM   112
#define HW     (HDIM * WDIM)          // 12544
#define NPIX   (NIMG * HW)            // 200704
#define KTOT   (CIN * 9)              // 1152

#define BM 128
#define BN 128
#define BK 32
#define NCHUNK 36                     // KTOT / BK
#define NTHREADS 256

#define APITCH 272                    // A: 256B data + 16B pad (conflict-free LDSM)
#define ATILE  8704                   // 32 k-rows * 272
#define BPITCH 80                     // B: 64B data + 16B pad (conflict-free LDSM)
#define BTILE  10240                  // 128 px-rows * 80
#define BUF_B  (ATILE + BTILE)        // 18944 per stage; 2 stages = 37888

// ---- persistent device scratch (__device__ globals are allowed) ----
__device__ __half nhwc_g[(size_t)NIMG * HW * CIN];        // input, NHWC fp16 (51.4 MB)
__device__ __half wh_g[2 * NCHUNK * 32 * (APITCH / 2)];   // weights pre-laid smem image

__device__ __forceinline__ uint32_t smem_u32(const void* p) {
    uint32_t a;
    asm("{.reg .u64 t; cvta.to.shared.u64 t, %1; cvt.u32.u64 %0, t;}" : "=r"(a) : "l"(p));
    return a;
}
__device__ __forceinline__ void ldsm_x4_t(uint32_t& r0, uint32_t& r1,
                                          uint32_t& r2, uint32_t& r3, uint32_t addr) {
    asm volatile("ldmatrix.sync.aligned.m8n8.x4.trans.shared.b16 {%0,%1,%2,%3}, [%4];"
                 : "=r"(r0), "=r"(r1), "=r"(r2), "=r"(r3) : "r"(addr));
}
__device__ __forceinline__ void ldsm_x4(uint32_t& r0, uint32_t& r1,
                                        uint32_t& r2, uint32_t& r3, uint32_t addr) {
    asm volatile("ldmatrix.sync.aligned.m8n8.x4.shared.b16 {%0,%1,%2,%3}, [%4];"
                 : "=r"(r0), "=r"(r1), "=r"(r2), "=r"(r3) : "r"(addr));
}
__device__ __forceinline__ void mma16816(float& d0, float& d1, float& d2, float& d3,
                                         uint32_t a0, uint32_t a1, uint32_t a2, uint32_t a3,
                                         uint32_t b0, uint32_t b1) {
    asm volatile(
        "mma.sync.aligned.m16n8k16.row.col.f32.f16.f16.f32 "
        "{%0,%1,%2,%3}, {%4,%5,%6,%7}, {%8,%9}, {%0,%1,%2,%3};"
        : "+f"(d0), "+f"(d1), "+f"(d2), "+f"(d3)
        : "r"(a0), "r"(a1), "r"(a2), "r"(a3), "r"(b0), "r"(b1));
}
__device__ __forceinline__ void cp16(uint32_t dst, const void* src) {
    asm volatile("cp.async.cg.shared.global [%0], [%1], 16;" :: "r"(dst), "l"(src) : "memory");
}

// ---------------- prologue 1: NCHW fp32 -> NHWC fp16 ----------------
// block: one (ni, cin-block of 32, hw-tile of 64); 12544 blocks, 256 threads
__global__ void __launch_bounds__(256) k_nhwc(const float* __restrict__ in) {
    __shared__ __half s[32][66];   // [cin][hw], padded
    int bid = blockIdx.x;
    int hwt = bid % 196;
    int tmp = bid / 196;
    int cb  = tmp & 3;
    int ni  = tmp >> 2;
    int hw0 = hwt * 64;

    int ci = threadIdx.x >> 3;          // 0..31
    int ho = (threadIdx.x & 7) * 8;     // 0..56
    const float* src = in + ((size_t)(ni * CIN + cb * 32 + ci)) * HW + hw0 + ho;
    float4 f0 = *(const float4*)src;
    float4 f1 = *(const float4*)(src + 4);
    s[ci][ho + 0] = __float2half_rn(f0.x);
    s[ci][ho + 1] = __float2half_rn(f0.y);
    s[ci][ho + 2] = __float2half_rn(f0.z);
    s[ci][ho + 3] = __float2half_rn(f0.w);
    s[ci][ho + 4] = __float2half_rn(f1.x);
    s[ci][ho + 5] = __float2half_rn(f1.y);
    s[ci][ho + 6] = __float2half_rn(f1.z);
    s[ci][ho + 7] = __float2half_rn(f1.w);
    __syncthreads();

    int hw  = threadIdx.x >> 2;          // 0..63
    int sub = (threadIdx.x & 3) * 8;     // 0,8,16,24
    __half t8[8];
    #pragma unroll
    for (int j = 0; j < 8; j++) t8[j] = s[sub + j][hw];
    __half* dst = nhwc_g + ((size_t)(ni * HW + hw0 + hw)) * CIN + cb * 32 + sub;
    *(uint4*)dst = *(const uint4*)t8;
}

// ---------------- prologue 2: weights -> pre-laid smem image ----------------
// wh_g[((bm*36 + c)*32 + r)*136 + m], kg = c*32 + r = (kh*3+kw)*128 + cin
__global__ void __launch_bounds__(256) k_layout_w(const float* __restrict__ wgt) {
    int idx = blockIdx.x * 256 + threadIdx.x;      // 294912 total
    int m   = idx & 127;
    int r   = (idx >> 7) & 31;
    int t   = idx >> 12;                           // bm*36 + c
    int c   = t % NCHUNK;
    int bm  = t / NCHUNK;
    int kg  = c * 32 + r;
    int cin = kg & 127;
    int kidx = kg >> 7;                            // kh*3 + kw
    float v = wgt[(bm * BM + m) * KTOT + cin * 9 + kidx];
    wh_g[((size_t)t * 32 + r) * (APITCH / 2) + m] = __float2half_rn(v);
}

// ---------------- main conv kernel ----------------
__global__ void __launch_bounds__(NTHREADS, 2)
conv_mma(const float* __restrict__ bias, float* __restrict__ out)
{
    __shared__ __align__(16) char smem[2 * BUF_B];
    const uint32_t sbase = smem_u32(smem);
    const int tid  = threadIdx.x;
    const int lane = tid & 31;
    const int wp   = tid >> 5;
    const int wm   = wp & 1;            // m half (64)
    const int wn   = wp >> 1;           // n quarter (32)
    const int bn   = blockIdx.x;        // pixel tile (whole tile is in one image)
    const int bm   = blockIdx.y;        // cout tile

    // ---- B gather: one pixel per thread (px = tid&127), cin-sub per half-block
    const int px  = tid & 127;
    const int sub = tid >> 7;           // 0/1 -> cin halves [0,16) / [16,32) of chunk
    const int pg  = bn * BN + px;
    const int ni  = pg / HW;
    const int hw  = pg - ni * HW;
    const int gh  = hw / WDIM;
    const int gw  = hw - gh * WDIM;
    const __half* psrc = nhwc_g + ((size_t)(ni * HW + hw)) * CIN + sub * 16;

    // ---- LDSM lane offsets
    const uint32_t aoff = (uint32_t)(((lane & 7) + ((lane >> 4) << 3)) * APITCH
                                     + ((lane >> 3) & 1) * 16);
    const uint32_t boff = (uint32_t)(((lane & 7) + ((lane >> 4) << 3)) * BPITCH
                                     + ((lane >> 3) & 1) * 16);

    const char* wh_src = (const char*)wh_g + (size_t)(bm * NCHUNK) * ATILE;

    float acc[4][4][4];
    #pragma unroll
    for (int mi = 0; mi < 4; mi++)
        #pragma unroll
        for (int ni_ = 0; ni_ < 4; ni_++)
            #pragma unroll
            for (int e = 0; e < 4; e++)
                acc[mi][ni_][e] = 0.0f;

    // B gather for chunk c into stage buffer (2 x LDG.128 + 2 x STS.128)
    auto gatherB = [&](int c, char* bdst) {
        int kidx = c >> 2;
        int cb   = (c & 3) * 32;
        int q3   = kidx / 3;
        int dh   = q3 - 1;
        int dw   = kidx - q3 * 3 - 1;
        bool vld = ((unsigned)(gh + dh) < (unsigned)HDIM) &&
                   ((unsigned)(gw + dw) < (unsigned)WDIM);
        const __half* src = psrc + (size_t)(dh * WDIM + dw) * CIN + cb;
        uint4 x0 = make_uint4(0, 0, 0, 0), x1 = x0;
        if (vld) {
            x0 = __ldg((const uint4*)src);
            x1 = __ldg((const uint4*)(src + 8));
        }
        char* d = bdst + px * BPITCH + sub * 32;
        *(uint4*)d        = x0;
        *(uint4*)(d + 16) = x1;
    };
    // A tile via cp.async (contiguous pre-laid 8704B block)
    auto loadA = [&](int c, uint32_t adst) {
        const char* src = wh_src + (size_t)c * ATILE;
        for (int u = tid; u < ATILE / 16; u += NTHREADS)
            cp16(adst + u * 16, src + u * 16);
    };

    // ---- preload chunk 0
    loadA(0, sbase);
    gatherB(0, smem + ATILE);
    asm volatile("cp.async.commit_group;" ::: "memory");
    asm volatile("cp.async.wait_group 0;" ::: "memory");
    __syncthreads();

    int buf = 0;
    #pragma unroll 4
    for (int c = 0; c < NCHUNK; ++c) {
        const bool has_next = (c + 1 < NCHUNK);
        const int nb = buf ^ 1;

        if (has_next) {
            loadA(c + 1, sbase + nb * BUF_B);
            asm volatile("cp.async.commit_group;" ::: "memory");
            gatherB(c + 1, smem + nb * BUF_B + ATILE);
        }

        // ---- compute chunk c
        const uint32_t abuf = sbase + buf * BUF_B;
        const uint32_t bbuf = abuf + ATILE;
        #pragma unroll
        for (int s = 0; s < 2; ++s) {
            uint32_t a[4][4];
            #pragma unroll
            for (int mi = 0; mi < 4; mi++)
                ldsm_x4_t(a[mi][0], a[mi][1], a[mi][2], a[mi][3],
                          abuf + (uint32_t)(s * 16 * APITCH + (wm * 64 + mi * 16) * 2) + aoff);
            #pragma unroll
            for (int pr = 0; pr < 2; ++pr) {
                uint32_t b0, b1, b2, b3;
                ldsm_x4(b0, b1, b2, b3,
                        bbuf + (uint32_t)((wn * 32 + pr * 16) * BPITCH + s * 32) + boff);
                #pragma unroll
                for (int mi = 0; mi < 4; mi++) {
                    mma16816(acc[mi][pr*2][0], acc[mi][pr*2][1],
                             acc[mi][pr*2][2], acc[mi][pr*2][3],
                             a[mi][0], a[mi][1], a[mi][2], a[mi][3], b0, b1);
                    mma16816(acc[mi][pr*2+1][0], acc[mi][pr*2+1][1],
                             acc[mi][pr*2+1][2], acc[mi][pr*2+1][3],
                             a[mi][0], a[mi][1], a[mi][2], a[mi][3], b2, b3);
                }
            }
        }

        if (has_next) {
            asm volatile("cp.async.wait_group 0;" ::: "memory");
        }
        __syncthreads();
        buf = nb;
    }

    // ---- epilogue: direct fragment stores (float2, full sectors per quarter-warp)
    const int q  = lane >> 2;           // 0..7
    const int r2 = (lane & 3) * 2;      // 0,2,4,6

    int pixbase[4];
    #pragma unroll
    for (int ni_ = 0; ni_ < 4; ni_++) {
        int n    = wn * 32 + ni_ * 8 + r2;
        int p    = bn * BN + n;
        int pi   = p / HW;
        int prem = p - pi * HW;
        pixbase[ni_] = pi * (COUT * HW) + prem;
    }

    #pragma unroll
    for (int mi = 0; mi < 4; mi++) {
        const int m0 = bm * BM + wm * 64 + mi * 16 + q;
        const float bv0 = __ldg(bias + m0);
        const float bv1 = __ldg(bias + m0 + 8);
        #pragma unroll
        for (int ni_ = 0; ni_ < 4; ni_++) {
            float2 v0 = make_float2(acc[mi][ni_][0] + bv0, acc[mi][ni_][1] + bv0);
            float2 v1 = make_float2(acc[mi][ni_][2] + bv1, acc[mi][ni_][3] + bv1);
            *(float2*)(out + pixbase[ni_] + m0 * HW)       = v0;
            *(float2*)(out + pixbase[ni_] + (m0 + 8) * HW) = v1;
        }
    }
}

// Tail: extra tuple members, only if the flattened output includes them.
__global__ void tail_kernel(const int* __restrict__ patch,
                            const int* __restrict__ stride_p,
                            const int* __restrict__ ksize_p,
                            const int* __restrict__ ph_p,
                            const int* __restrict__ pw_p,
                            float* __restrict__ out,
                            int base, int n_extra)
{
    const int t = threadIdx.x;
    if (t < 32 && t < n_extra)
        out[base + t] = (float)patch[t];
    if (t == 32 && n_extra > 32) {
        int s = stride_p ? *stride_p : 1;
        int k = ksize_p  ? *ksize_p  : 3;
        int ph = ph_p    ? *ph_p     : 8;
        int x = ph + k - 1;
        out[base + 32] = (float)((x + s - 1) / s);
    }
    if (t == 33 && n_extra > 33) {
        int s = stride_p ? *stride_p : 1;
        int k = ksize_p  ? *ksize_p  : 3;
        int pw = pw_p    ? *pw_p     : 8;
        int x = pw + k - 1;
        out[base + 33] = (float)((x + s - 1) / s);
    }
}

extern "C" void kernel_launch(void* const* d_in, const int* in_sizes, int n_in,
                              void* d_out, int out_size)
{
    const float* in   = (const float*)d_in[0];
    const float* wgt  = (const float*)d_in[1];
    const float* bias = (const float*)d_in[2];
    const int* patch  = (const int*)d_in[4];
    float* out = (float*)d_out;

    k_nhwc<<<NIMG * 4 * 196, 256>>>(in);
    k_layout_w<<<2 * NCHUNK * 32 * 128 / 256, 256>>>(wgt);

    dim3 grid(NPIX / BN, COUT / BM);   // 1568 x 2
    conv_mma<<<grid, NTHREADS>>>(bias, out);

    const int convN = in_sizes[3];     // N*Cout*H*W
    const int extra = out_size - convN;
    if (extra > 0) {
        const int* sp  = (n_in > 6) ? (const int*)d_in[6] : nullptr;
        const int* kp  = (n_in > 7) ? (const int*)d_in[7] : nullptr;
        const int* php = (n_in > 8) ? (const int*)d_in[8] : nullptr;
        const int* pwp = (n_in > 9) ? (const int*)d_in[9] : nullptr;
        tail_kernel<<<1, 64>>>(patch, sp, kp, php, pwp, out, convN, extra);
    }
}

// round 7
// speedup vs baseline: 1.0821x; 1.0821x over previous
#include <cuda_runtime.h>
#include <cuda_fp16.h>
#include <cstdint>

// Problem constants (fixed by setup_inputs)
#define NIMG   16
#define CIN    128
#define COUT   256
#define HDIM   112
#define WDIM   112
#define HW     (HDIM * WDIM)          // 12544
#define NPIX   (NIMG * HW)            // 200704
#define KTOT   (CIN * 9)              // 1152

#define BM 128
#define BN 128
#define BK 32
#define NCHUNK 36                     // KTOT / BK
#define NTHREADS 256

#define PITCH  272                    // 256B data + 16B pad (conflict-free LDSM)
#define TILE_B 8704                   // 32 rows * 272
#define BUF_B  (2 * TILE_B)           // A + B per stage; 2 stages = 34816 B

// ---- persistent device scratch (__device__ globals are allowed) ----
__device__ __half inh_g[(size_t)NIMG * CIN * HW];         // input as fp16, NCHW (51.4 MB)
__device__ __half wh_g[2 * NCHUNK * 32 * (PITCH / 2)];    // weights pre-laid smem image

__device__ __forceinline__ uint32_t smem_u32(const void* p) {
    uint32_t a;
    asm("{.reg .u64 t; cvta.to.shared.u64 t, %1; cvt.u32.u64 %0, t;}" : "=r"(a) : "l"(p));
    return a;
}
__device__ __forceinline__ void ldsm_x4_t(uint32_t& r0, uint32_t& r1,
                                          uint32_t& r2, uint32_t& r3, uint32_t addr) {
    asm volatile("ldmatrix.sync.aligned.m8n8.x4.trans.shared.b16 {%0,%1,%2,%3}, [%4];"
                 : "=r"(r0), "=r"(r1), "=r"(r2), "=r"(r3) : "r"(addr));
}
__device__ __forceinline__ void mma16816(float& d0, float& d1, float& d2, float& d3,
                                         uint32_t a0, uint32_t a1, uint32_t a2, uint32_t a3,
                                         uint32_t b0, uint32_t b1) {
    asm volatile(
        "mma.sync.aligned.m16n8k16.row.col.f32.f16.f16.f32 "
        "{%0,%1,%2,%3}, {%4,%5,%6,%7}, {%8,%9}, {%0,%1,%2,%3};"
        : "+f"(d0), "+f"(d1), "+f"(d2), "+f"(d3)
        : "r"(a0), "r"(a1), "r"(a2), "r"(a3), "r"(b0), "r"(b1));
}
__device__ __forceinline__ void cp16(uint32_t dst, const void* src) {
    asm volatile("cp.async.cg.shared.global [%0], [%1], 16;" :: "r"(dst), "l"(src) : "memory");
}

// ---------------- prologue 1: input fp32 -> fp16 (same NCHW layout) ----------------
__global__ void __launch_bounds__(256) k_cvt_input(const float* __restrict__ in) {
    int i = blockIdx.x * 256 + threadIdx.x;        // one uint4 (8 halves) per thread
    const float4* in4 = (const float4*)in;
    float4 f0 = in4[i * 2];
    float4 f1 = in4[i * 2 + 1];
    __half h[8];
    h[0] = __float2half_rn(f0.x); h[1] = __float2half_rn(f0.y);
    h[2] = __float2half_rn(f0.z); h[3] = __float2half_rn(f0.w);
    h[4] = __float2half_rn(f1.x); h[5] = __float2half_rn(f1.y);
    h[6] = __float2half_rn(f1.z); h[7] = __float2half_rn(f1.w);
    ((uint4*)inh_g)[i] = *(const uint4*)h;
}

// ---------------- prologue 2: weights -> pre-laid smem image ----------------
// wh_g[((bm*36 + c)*32 + r)*136 + m], kg = c*32 + r = (kh*3+kw)*128 + cin
__global__ void __launch_bounds__(256) k_layout_w(const float* __restrict__ wgt) {
    int idx = blockIdx.x * 256 + threadIdx.x;      // 294912 total
    int m   = idx & 127;
    int r   = (idx >> 7) & 31;
    int t   = idx >> 12;                           // bm*36 + c
    int c   = t % NCHUNK;
    int bm  = t / NCHUNK;
    int kg  = c * 32 + r;
    int cin = kg & 127;
    int kidx = kg >> 7;                            // kh*3 + kw
    float v = wgt[(bm * BM + m) * KTOT + cin * 9 + kidx];
    wh_g[((size_t)t * 32 + r) * (PITCH / 2) + m] = __float2half_rn(v);
}

// ---------------- main conv kernel ----------------
__global__ void __launch_bounds__(NTHREADS, 2)
conv_mma(const float* __restrict__ bias, float* __restrict__ out)
{
    __shared__ __align__(16) char smem[2 * BUF_B];
    const uint32_t sbase = smem_u32(smem);
    const int tid  = threadIdx.x;
    const int lane = tid & 31;
    const int wp   = tid >> 5;
    const int wm   = wp & 1;            // m half (64)
    const int wn   = wp >> 1;           // n quarter (32)
    const int bn   = blockIdx.x;        // pixel tile (whole tile in one image: 12544%128==0)
    const int bm   = blockIdx.y;        // cout tile

    // ---- B gather mapping: 8-pixel group g, two k-rows (rr, rr+16) per thread
    const int g   = tid & 15;           // pixel group within tile
    const int rr  = tid >> 4;           // 0..15
    const int pg0 = bn * BN;
    const int ni  = pg0 / HW;
    const int hwb = pg0 - ni * HW;
    const int hw0 = hwb + g * 8;        // 8-aligned; 112%8==0 -> group shares h
    const int h0  = hw0 / WDIM;
    const int w0  = hw0 - h0 * WDIM;
    const __half* imgbase = inh_g + (size_t)ni * CIN * HW;
    const bool eL = (w0 != 0);          // edge word valid for dw=-1
    const bool eR = (w0 != 104);        // edge word valid for dw=+1

    // ---- LDSM lane offsets (identical to the passing R5 kernel)
    const uint32_t aoff = (uint32_t)(((lane & 7) + ((lane >> 4) << 3)) * PITCH
                                     + ((lane >> 3) & 1) * 16);
    const uint32_t boff = (uint32_t)(((lane & 7) + (((lane >> 3) & 1) << 3)) * PITCH
                                     + (lane >> 4) * 16);

    const char* wh_src = (const char*)wh_g + (size_t)(bm * NCHUNK) * TILE_B;

    float acc[4][4][4];
    #pragma unroll
    for (int mi = 0; mi < 4; mi++)
        #pragma unroll
        for (int ni_ = 0; ni_ < 4; ni_++)
            #pragma unroll
            for (int e = 0; e < 4; e++)
                acc[mi][ni_][e] = 0.0f;

    // B gather for chunk c: vectorized along pixels, funnel-shift for dw=+/-1
    auto gatherB = [&](int c, char* bdst) {
        int kidx = c >> 2;
        int q3   = kidx / 3;
        int dh   = q3 - 1;
        int dw   = kidx - q3 * 3 - 1;
        int cb   = (c & 3) * 32;
        bool vrow = ((unsigned)(h0 + dh) < (unsigned)HDIM);
        int q0 = hw0 + dh * WDIM;        // aligned window base (16B aligned: 112*2=224=14*16)
        #pragma unroll
        for (int rep = 0; rep < 2; rep++) {
            int r = rr + rep * 16;       // local k row = cin offset within chunk
            const __half* src = imgbase + (size_t)(cb + r) * HW + q0;
            uint4 X = make_uint4(0, 0, 0, 0);
            uint32_t E = 0;
            if (vrow) {
                X = __ldg((const uint4*)src);
                if (dw > 0) { if (eR) E = __ldg((const uint32_t*)(src + 8)); }
                else if (dw < 0) { if (eL) E = __ldg((const uint32_t*)(src - 2)); }
            }
            uint4 Y;
            if (dw == 0) {
                Y = X;
            } else if (dw > 0) {         // window [q0+1, q0+9): shift right one half
                Y.x = __funnelshift_r(X.x, X.y, 16);
                Y.y = __funnelshift_r(X.y, X.z, 16);
                Y.z = __funnelshift_r(X.z, X.w, 16);
                Y.w = __funnelshift_r(X.w, E, 16);   // E==0 at right edge -> pad zero
            } else {                     // window [q0-1, q0+7): shift left one half
                Y.x = __funnelshift_r(E, X.x, 16);   // E==0 at left edge -> pad zero
                Y.y = __funnelshift_r(X.x, X.y, 16);
                Y.z = __funnelshift_r(X.y, X.z, 16);
                Y.w = __funnelshift_r(X.z, X.w, 16);
            }
            // dw=-1 uses high halves of (E,X): funnelshift_r(lo,hi,16) = lo>>16 | hi<<16
            *(uint4*)(bdst + r * PITCH + g * 16) = Y;
        }
    };
    // A tile via cp.async (contiguous pre-laid 8704B block)
    auto loadA = [&](int c, uint32_t adst) {
        const char* src = wh_src + (size_t)c * TILE_B;
        for (int u = tid; u < TILE_B / 16; u += NTHREADS)
            cp16(adst + u * 16, src + u * 16);
    };

    // ---- preload chunk 0
    loadA(0, sbase);
    gatherB(0, smem + TILE_B);
    asm volatile("cp.async.commit_group;" ::: "memory");
    asm volatile("cp.async.wait_group 0;" ::: "memory");
    __syncthreads();

    int buf = 0;
    #pragma unroll 4
    for (int c = 0; c < NCHUNK; ++c) {
        const bool has_next = (c + 1 < NCHUNK);
        const int nb = buf ^ 1;

        if (has_next) {
            loadA(c + 1, sbase + nb * BUF_B);
            asm volatile("cp.async.commit_group;" ::: "memory");
            gatherB(c + 1, smem + nb * BUF_B + TILE_B);
        }

        // ---- compute chunk c (identical to R5's passing kernel)
        const uint32_t abuf = sbase + buf * BUF_B;
        const uint32_t bbuf = abuf + TILE_B;
        #pragma unroll
        for (int s = 0; s < 2; ++s) {
            uint32_t a[4][4];
            #pragma unroll
            for (int mi = 0; mi < 4; mi++)
                ldsm_x4_t(a[mi][0], a[mi][1], a[mi][2], a[mi][3],
                          abuf + (uint32_t)(s * 16 * PITCH + (wm * 64 + mi * 16) * 2) + aoff);
            #pragma unroll
            for (int pr = 0; pr < 2; ++pr) {
                uint32_t b[4];
                ldsm_x4_t(b[0], b[1], b[2], b[3],
                          bbuf + (uint32_t)(s * 16 * PITCH + (wn * 32 + pr * 16) * 2) + boff);
                #pragma unroll
                for (int mi = 0; mi < 4; mi++) {
                    mma16816(acc[mi][pr*2][0], acc[mi][pr*2][1],
                             acc[mi][pr*2][2], acc[mi][pr*2][3],
                             a[mi][0], a[mi][1], a[mi][2], a[mi][3], b[0], b[1]);
                    mma16816(acc[mi][pr*2+1][0], acc[mi][pr*2+1][1],
                             acc[mi][pr*2+1][2], acc[mi][pr*2+1][3],
                             a[mi][0], a[mi][1], a[mi][2], a[mi][3], b[2], b[3]);
                }
            }
        }

        if (has_next) {
            asm volatile("cp.async.wait_group 0;" ::: "memory");
        }
        __syncthreads();
        buf = nb;
    }

    // ---- epilogue: direct fragment stores (float2, full sectors per quarter-warp)
    const int q  = lane >> 2;           // 0..7
    const int r2 = (lane & 3) * 2;      // 0,2,4,6

    int pixbase[4];
    #pragma unroll
    for (int ni_ = 0; ni_ < 4; ni_++) {
        int n    = wn * 32 + ni_ * 8 + r2;
        int p    = bn * BN + n;
        int pi   = p / HW;
        int prem = p - pi * HW;
        pixbase[ni_] = pi * (COUT * HW) + prem;
    }

    #pragma unroll
    for (int mi = 0; mi < 4; mi++) {
        const int m0 = bm * BM + wm * 64 + mi * 16 + q;
        const float bv0 = __ldg(bias + m0);
        const float bv1 = __ldg(bias + m0 + 8);
        #pragma unroll
        for (int ni_ = 0; ni_ < 4; ni_++) {
            float2 v0 = make_float2(acc[mi][ni_][0] + bv0, acc[mi][ni_][1] + bv0);
            float2 v1 = make_float2(acc[mi][ni_][2] + bv1, acc[mi][ni_][3] + bv1);
            *(float2*)(out + pixbase[ni_] + m0 * HW)       = v0;
            *(float2*)(out + pixbase[ni_] + (m0 + 8) * HW) = v1;
        }
    }
}

// Tail: extra tuple members, only if the flattened output includes them.
__global__ void tail_kernel(const int* __restrict__ patch,
                            const int* __restrict__ stride_p,
                            const int* __restrict__ ksize_p,
                            const int* __restrict__ ph_p,
                            const int* __restrict__ pw_p,
                            float* __restrict__ out,
                            int base, int n_extra)
{
    const int t = threadIdx.x;
    if (t < 32 && t < n_extra)
        out[base + t] = (float)patch[t];
    if (t == 32 && n_extra > 32) {
        int s = stride_p ? *stride_p : 1;
        int k = ksize_p  ? *ksize_p  : 3;
        int ph = ph_p    ? *ph_p     : 8;
        int x = ph + k - 1;
        out[base + 32] = (float)((x + s - 1) / s);
    }
    if (t == 33 && n_extra > 33) {
        int s = stride_p ? *stride_p : 1;
        int k = ksize_p  ? *ksize_p  : 3;
        int pw = pw_p    ? *pw_p     : 8;
        int x = pw + k - 1;
        out[base + 33] = (float)((x + s - 1) / s);
    }
}

extern "C" void kernel_launch(void* const* d_in, const int* in_sizes, int n_in,
                              void* d_out, int out_size)
{
    const float* in   = (const float*)d_in[0];
    const float* wgt  = (const float*)d_in[1];
    const float* bias = (const float*)d_in[2];
    const int* patch  = (const int*)d_in[4];
    float* out = (float*)d_out;

    k_cvt_input<<<NIMG * CIN * HW / (256 * 8), 256>>>(in);
    k_layout_w<<<2 * NCHUNK * 32 * 128 / 256, 256>>>(wgt);

    dim3 grid(NPIX / BN, COUT / BM);   // 1568 x 2
    conv_mma<<<grid, NTHREADS>>>(bias, out);

    const int convN = in_sizes[3];     // N*Cout*H*W
    const int extra = out_size - convN;
    if (extra > 0) {
        const int* sp  = (n_in > 6) ? (const int*)d_in[6] : nullptr;
        const int* kp  = (n_in > 7) ? (const int*)d_in[7] : nullptr;
        const int* php = (n_in > 8) ? (const int*)d_in[8] : nullptr;
        const int* pwp = (n_in > 9) ? (const int*)d_in[9] : nullptr;
        tail_kernel<<<1, 64>>>(patch, sp, kp, php, pwp, out, convN, extra);
    }
}